// round 9
// baseline (speedup 1.0000x reference)
#include <cuda_runtime.h>
#include <cstdint>

// Problem constants
#define NLEN   8192
#define LOGN   13
#define MODES  1024
#define BATCH  32
#define CIN    64
#define COUT   64
#define IROWS  (BATCH*CIN)    // 2048 input rows
#define OROWS  (BATCH*COUT)   // 2048 output rows

// -------- scratch (no allocations allowed; use __device__ globals) --------
// cas table [0, 8192]: tab[k] = cas(2*pi*k/8192)  (phase B / stage 9 only)
__device__ __align__(32) float g_tab[8200];
// tiled-mode layouts: [mtile = m>>3][row][m&7]  (32B sector = 8 modes of one row)
__device__ __align__(16) float g_xmP[128 * IROWS * 8];   // 8 MB
__device__ __align__(16) float g_zP [128 * OROWS * 8];   // 8 MB

// GF(2)-linear smem swizzle. k0^=u5^u9, k1^=u6^u10, k2^=u7^u11, k3^=u8, k4^=u8^u12.
__device__ __forceinline__ int swz(int u) {
    int f = ((u >> 5) & 7) ^ ((u >> 9) & 7)
          ^ (((u >> 8) & 1) * 0x18)
          ^ (((u >> 12) & 1) * 0x10);
    return u ^ f;
}
__device__ __forceinline__ int rev9(int t) { return (int)(__brev((unsigned)t) >> 23); }

// Literal cas values
#define RSQ2  0.70710678118654752f
#define C8L   0.92387953251128674f
#define S8L   0.38268343236508977f
#define THETA0 7.66990393942820615e-4f   // pi/4096

// Packed f32x2 helpers (Blackwell)
typedef unsigned long long ull_t;
__device__ __forceinline__ ull_t pack2(float x) {
    ull_t r; asm("mov.b64 %0, {%1, %1};" : "=l"(r) : "f"(x)); return r;
}
__device__ __forceinline__ ull_t fma2(ull_t a, ull_t b, ull_t c) {
    ull_t d; asm("fma.rn.f32x2 %0, %1, %2, %3;" : "=l"(d) : "l"(a), "l"(b), "l"(c));
    return d;
}
__device__ __forceinline__ void unpack2(ull_t v, float& lo, float& hi) {
    asm("mov.b64 {%0, %1}, %2;" : "=f"(lo), "=f"(hi) : "l"(v));
}

// Phase-C twiddles via MUFU + double-angle (no memory traffic).
struct CTw { float c13p, c13m, c12p, c12m, c11p, c11m, c10; };
__device__ __forceinline__ CTw ctw(int t) {
    float s1, c1;
    __sincosf((float)t * THETA0, &s1, &c1);
    CTw w;
    w.c13p = c1 + s1;  w.c13m = c1 - s1;
    float s2 = 2.0f * s1 * c1, c2 = fmaf(-2.0f * s1, s1, 1.0f);
    w.c12p = c2 + s2;  w.c12m = c2 - s2;
    float s4 = 2.0f * s2 * c2, c4 = fmaf(-2.0f * s2, s2, 1.0f);
    w.c11p = c4 + s4;  w.c11m = c4 - s4;
    float s8 = 2.0f * s4 * c4, c8 = fmaf(-2.0f * s4, s4, 1.0f);
    w.c10  = c8 + s8;
    return w;
}

// ---------------------------------------------------------------------------
__global__ void init_table_kernel() {
    int t = blockIdx.x * blockDim.x + threadIdx.x;
    if (t <= NLEN) {
        float s, c;
        sincospif((float)t * (1.0f / 4096.0f), &s, &c);
        g_tab[t] = c + s;
    }
}

// -------- Phase A stages 1-4: all twiddles are literals ---------------------
__device__ __forceinline__ void stagesA(float r[16]) {
    #pragma unroll
    for (int e = 0; e < 16; e += 2) {
        float o = r[e + 1]; r[e + 1] = r[e] - o; r[e] += o;
    }
    #pragma unroll
    for (int g = 0; g < 16; g += 4)
        #pragma unroll
        for (int e = g; e < g + 2; e++) {
            float o = r[e + 2]; r[e + 2] = r[e] - o; r[e] += o;
        }
    {
        const float c3[4] = {1.0f, 1.41421356237309515f, 1.0f, 0.0f};
        #pragma unroll
        for (int eb = 0; eb < 4; eb++)
            #pragma unroll
            for (int g = 0; g < 16; g += 8) {
                int e = g + eb;
                float o = c3[eb] * r[e + 4]; r[e + 4] = r[e] - o; r[e] += o;
            }
    }
    {
        const float c4[8] = {1.0f, 1.30656296487637653f, 1.41421356237309515f,
                             1.30656296487637653f, 1.0f, 0.54119610014619701f,
                             0.0f, -0.54119610014619701f};
        #pragma unroll
        for (int e = 0; e < 8; e++) {
            float o = c4[e] * r[e + 8]; r[e + 8] = r[e] - o; r[e] += o;
        }
    }
}

// -------- Phase B stages 5-9: twiddles warp-uniform; stage 9 via shfl -------
__device__ __forceinline__ void phaseB(float* sm, float r[16], int t,
                                       const float* __restrict__ tab) {
    const int wid  = t >> 5;
    const int lane = t & 31;
    const int base = (lane << 8) | wid;
    #pragma unroll
    for (int s = 0; s < 16; s++) r[s] = sm[swz(base | (s << 4))];
    {
        float cas = tab[wid << 8];
        #pragma unroll
        for (int s = 0; s < 16; s += 2) {
            float o = cas * r[s + 1]; r[s + 1] = r[s] - o; r[s] += o;
        }
    }
    #pragma unroll
    for (int sb = 0; sb < 2; sb++) {
        float cas = tab[((sb << 4) | wid) << 7];
        #pragma unroll
        for (int g = 0; g < 16; g += 4) {
            int s = g + sb;
            float o = cas * r[s + 2]; r[s + 2] = r[s] - o; r[s] += o;
        }
    }
    #pragma unroll
    for (int sb = 0; sb < 4; sb++) {
        float cas = tab[((sb << 4) | wid) << 6];
        #pragma unroll
        for (int g = 0; g < 16; g += 8) {
            int s = g + sb;
            float o = cas * r[s + 4]; r[s + 4] = r[s] - o; r[s] += o;
        }
    }
    #pragma unroll
    for (int s = 0; s < 8; s++) {
        float cas = tab[((s << 4) | wid) << 5];
        float o = cas * r[s + 8]; r[s + 8] = r[s] - o; r[s] += o;
    }
    {
        const bool odd = (lane & 1);
        #pragma unroll
        for (int s = 0; s < 16; s++) {
            float cas = tab[(s << 8) | (wid << 4)];
            float p = __shfl_xor_sync(0xFFFFFFFFu, r[s], 1);
            r[s] = odd ? (p - cas * r[s]) : fmaf(cas, p, r[s]);
        }
    }
    #pragma unroll
    for (int s = 0; s < 16; s++) sm[swz(base | (s << 4))] = r[s];
}

// -------- forward: x[row][0..8192) -> xmP tiles ------------------------------
__global__ __launch_bounds__(512, 2) void fht_fwd_kernel(const float* __restrict__ x) {
    __shared__ float sm[NLEN];
    const int row = blockIdx.x;
    const int t = threadIdx.x;
    const float* __restrict__ tab = g_tab;
    const float* __restrict__ xr = x + (size_t)row * NLEN;

    float r[16];
    {
        const int REV4[16] = {0,8,4,12, 2,10,6,14, 1,9,5,13, 3,11,7,15};
        #pragma unroll
        for (int e = 0; e < 16; e++) r[REV4[e]] = xr[e * 512 + t];
        stagesA(r);
        const int ub = rev9(t) << 4;
        #pragma unroll
        for (int e = 0; e < 16; e++) sm[swz(ub | e)] = r[e];
    }
    __syncthreads();

    phaseB(sm, r, t, tab);
    __syncthreads();

    // Phase C: u = s<<9 | t; stages 10-13 in registers, 11-13 pruned (m<1024)
    {
        CTw w = ctw(t);
        #pragma unroll
        for (int s = 0; s < 16; s++) r[s] = sm[swz((s << 9) | t)];
        #pragma unroll
        for (int s = 0; s < 16; s += 2) {
            float o = w.c10 * r[s + 1]; r[s + 1] = r[s] - o; r[s] += o;
        }
        {
            const float w11[2] = { w.c11p, w.c11m };
            #pragma unroll
            for (int g = 0; g < 16; g += 4)
                #pragma unroll
                for (int sb = 0; sb < 2; sb++)
                    r[g + sb] += w11[sb] * r[g + sb + 2];
        }
        {
            const float w12[2] = { w.c12p, RSQ2 * (w.c12p + w.c12m) };
            #pragma unroll
            for (int g = 0; g < 16; g += 8)
                #pragma unroll
                for (int sb = 0; sb < 2; sb++)
                    r[g + sb] += w12[sb] * r[g + sb + 4];
        }
        r[0] += w.c13p * r[8];
        r[1] += (C8L * w.c13p + S8L * w.c13m) * r[9];

        // tiled store: mode m -> g_xmP[m>>3][row][m&7]  (4 x 32B sectors / warp)
        g_xmP[((size_t)(t >> 3) * IROWS + row) * 8 + (t & 7)]        = r[0];
        g_xmP[((size_t)((t >> 3) + 64) * IROWS + row) * 8 + (t & 7)] = r[1];
    }
}

// -------- inverse: zP tiles -> out[row][0..8192)/8192 ------------------------
__global__ __launch_bounds__(512, 2) void fht_inv_kernel(float* __restrict__ out) {
    __shared__ float sm[NLEN];
    const int row = blockIdx.x;
    const int t = threadIdx.x;
    const float* __restrict__ tab = g_tab;

    {
        float v0 = g_zP[((size_t)(t >> 3) * OROWS + row) * 8 + (t & 7)];
        float v1 = g_zP[((size_t)((t >> 3) + 64) * OROWS + row) * 8 + (t & 7)];
        const int ub = rev9(t) << 4;
        const float c4[8] = {1.0f, 1.30656296487637653f, 1.41421356237309515f,
                             1.30656296487637653f, 1.0f, 0.54119610014619701f,
                             0.0f, -0.54119610014619701f};
        #pragma unroll
        for (int e = 0; e < 8; e++) {
            float o = c4[e] * v1;
            sm[swz(ub | e)]       = v0 + o;
            sm[swz(ub | (e + 8))] = v0 - o;
        }
    }
    __syncthreads();

    float r[16];
    phaseB(sm, r, t, tab);
    __syncthreads();

    {
        CTw w = ctw(t);
        #pragma unroll
        for (int s = 0; s < 16; s++) r[s] = sm[swz((s << 9) | t)];
        #pragma unroll
        for (int s = 0; s < 16; s += 2) {
            float o = w.c10 * r[s + 1]; r[s + 1] = r[s] - o; r[s] += o;
        }
        {
            const float w11[2] = { w.c11p, w.c11m };
            #pragma unroll
            for (int g = 0; g < 16; g += 4)
                #pragma unroll
                for (int sb = 0; sb < 2; sb++) {
                    int s = g + sb;
                    float o = w11[sb] * r[s + 2]; r[s + 2] = r[s] - o; r[s] += o;
                }
        }
        {
            const float w12[4] = { w.c12p, RSQ2 * (w.c12p + w.c12m),
                                   w.c12m, RSQ2 * (w.c12m - w.c12p) };
            #pragma unroll
            for (int g = 0; g < 16; g += 8)
                #pragma unroll
                for (int sb = 0; sb < 4; sb++) {
                    int s = g + sb;
                    float o = w12[sb] * r[s + 4]; r[s + 4] = r[s] - o; r[s] += o;
                }
        }
        {
            const float CS[8] = {1.0f, C8L, RSQ2, S8L, 0.0f, -S8L, -RSQ2, -C8L};
            const float SN[8] = {0.0f, S8L, RSQ2, C8L, 1.0f,  C8L,  RSQ2,  S8L};
            #pragma unroll
            for (int s = 0; s < 8; s++) {
                float w13 = CS[s] * w.c13p + SN[s] * w.c13m;
                float o = w13 * r[s + 8]; r[s + 8] = r[s] - o; r[s] += o;
            }
        }
        const float scale = 1.0f / (float)NLEN;
        float* __restrict__ orow = out + (size_t)row * NLEN;
        #pragma unroll
        for (int s = 0; s < 16; s++)
            orow[(s << 9) | t] = r[s] * scale;
    }
}

// -------- transpose-free tiled mix -------------------------------------------
// Block (mt, oc): M-modes [16mt, 16mt+16), mt = 0..32; pair p(m) = (1024-m)&1023.
// A(m) = sum_i a*w[i,o,m] + d*w[i,o,p]   written for all m in [0,528)
// B(p) = sum_i a*w[i,o,p] - d*w[i,o,m]   written only for p >= 528
// (coverage: [0,528) u [528,1024) = all modes; no duplicate writes)
// Threads 256: bq = tid&15 (batch), mg = (tid>>4)&3 (4-mode group), oq = tid>>6.
// Thread tile: 2 batches (bq, bq+16) x 4 outs (oq+4*oo) x 4 modes (2 f32x2 pairs).
#define MIX_CI 4
__global__ __launch_bounds__(256) void mix_kernel(const float* __restrict__ w) {
    __shared__ float s_w0[MIX_CI][16][18];   // [i'][o_local][ml] stride 18: 8B-aligned,
    __shared__ float s_w1[MIX_CI][16][18];   //   conflict-free LDS.64 (18*bq mod 32 distinct)
    __shared__ float s_a [MIX_CI][32][18];   // [i'][b][ml]
    __shared__ float s_d [MIX_CI][32][18];

    const int mt = blockIdx.x;        // 0..32
    const int oc = blockIdx.y;        // 0..3
    const int o0 = oc * 16;
    const int m0 = mt * 16;
    const int tid = threadIdx.x;
    const int bq = tid & 15;
    const int mg = (tid >> 4) & 3;
    const int oq = tid >> 6;

    ull_t A[2][4][2], B[2][4][2];
    #pragma unroll
    for (int bb = 0; bb < 2; bb++)
        #pragma unroll
        for (int oo = 0; oo < 4; oo++)
            #pragma unroll
            for (int k = 0; k < 2; k++) { A[bb][oo][k] = 0ull; B[bb][oo][k] = 0ull; }

    // fill decode (independent of consume decode)
    const int f_ii = tid >> 6;        // 0..3
    const int f_r  = tid & 63;
    const int f_ol = f_r >> 2;        // 0..15
    const int f_mq = f_r & 3;         // 0..3
    const int f_b  = f_r >> 1;        // 0..31
    const int f_mh = f_r & 1;         // 0..1

    #pragma unroll 1
    for (int c = 0; c < 16; c++) {
        const int i0 = c * 4;
        if (c) __syncthreads();
        // ---- stage weights (w native layout: m innermost -> coalesced) ----
        {
            const float* wrow = w + ((size_t)((i0 + f_ii) * 64 + (o0 + f_ol)) << 10);
            float4 v = *(const float4*)&wrow[m0 + 4 * f_mq];
            s_w0[f_ii][f_ol][4*f_mq + 0] = v.x;
            s_w0[f_ii][f_ol][4*f_mq + 1] = v.y;
            s_w0[f_ii][f_ol][4*f_mq + 2] = v.z;
            s_w0[f_ii][f_ol][4*f_mq + 3] = v.w;
            #pragma unroll
            for (int j = 0; j < 4; j++) {
                int ml = 4 * f_mq + j;
                int p = (1024 - (m0 + ml)) & 1023;
                s_w1[f_ii][f_ol][ml] = wrow[p];
            }
        }
        // ---- stage a/d from tiled xmP ----
        {
            const int row = f_b * 64 + i0 + f_ii;
            const float* xt = g_xmP + ((size_t)(2 * mt + f_mh) * IROWS + row) * 8;
            float4 xa = *(const float4*)&xt[0];
            float4 xb = *(const float4*)&xt[4];
            float xM[8] = {xa.x, xa.y, xa.z, xa.w, xb.x, xb.y, xb.z, xb.w};
            #pragma unroll
            for (int j = 0; j < 8; j++) {
                int ml = 8 * f_mh + j;
                int p = (1024 - (m0 + ml)) & 1023;
                float xP = g_xmP[((size_t)(p >> 3) * IROWS + row) * 8 + (p & 7)];
                s_a[f_ii][f_b][ml] = 0.5f * (xM[j] + xP);
                s_d[f_ii][f_b][ml] = 0.5f * (xM[j] - xP);
            }
        }
        __syncthreads();
        // ---- consume ----
        #pragma unroll
        for (int ii = 0; ii < MIX_CI; ii++) {
            ull_t aa[2][2], dd[2][2], nd[2][2];
            #pragma unroll
            for (int bb = 0; bb < 2; bb++) {
                int b = bq + 16 * bb;
                #pragma unroll
                for (int k = 0; k < 2; k++) {
                    aa[bb][k] = *(const ull_t*)&s_a[ii][b][4*mg + 2*k];
                    dd[bb][k] = *(const ull_t*)&s_d[ii][b][4*mg + 2*k];
                    nd[bb][k] = dd[bb][k] ^ 0x8000000080000000ull;
                }
            }
            #pragma unroll
            for (int oo = 0; oo < 4; oo++) {
                int ol = oq + 4 * oo;
                #pragma unroll
                for (int k = 0; k < 2; k++) {
                    ull_t w0v = *(const ull_t*)&s_w0[ii][ol][4*mg + 2*k];
                    ull_t w1v = *(const ull_t*)&s_w1[ii][ol][4*mg + 2*k];
                    #pragma unroll
                    for (int bb = 0; bb < 2; bb++) {
                        A[bb][oo][k] = fma2(aa[bb][k], w0v, A[bb][oo][k]);
                        A[bb][oo][k] = fma2(dd[bb][k], w1v, A[bb][oo][k]);
                        B[bb][oo][k] = fma2(aa[bb][k], w1v, B[bb][oo][k]);
                        B[bb][oo][k] = fma2(nd[bb][k], w0v, B[bb][oo][k]);
                    }
                }
            }
        }
    }

    // ---- stores ----
    const int tileA = (m0 + 4 * mg) >> 3;
    const int offA  = (4 * mg) & 7;
    #pragma unroll
    for (int bb = 0; bb < 2; bb++) {
        int b = bq + 16 * bb;
        #pragma unroll
        for (int oo = 0; oo < 4; oo++) {
            int og = o0 + oq + 4 * oo;
            int row = b * 64 + og;
            float4 v;
            unpack2(A[bb][oo][0], v.x, v.y);
            unpack2(A[bb][oo][1], v.z, v.w);
            *(float4*)&g_zP[((size_t)tileA * OROWS + row) * 8 + offA] = v;
            #pragma unroll
            for (int k = 0; k < 2; k++) {
                float lo, hi;
                unpack2(B[bb][oo][k], lo, hi);
                int m_lo = m0 + 4 * mg + 2 * k;
                int plo = (1024 - m_lo) & 1023;
                int phi_ = (1024 - (m_lo + 1)) & 1023;
                if (plo >= 528)
                    g_zP[((size_t)(plo >> 3) * OROWS + row) * 8 + (plo & 7)] = lo;
                if (phi_ >= 528)
                    g_zP[((size_t)(phi_ >> 3) * OROWS + row) * 8 + (phi_ & 7)] = hi;
            }
        }
    }
}

// ---------------------------------------------------------------------------
extern "C" void kernel_launch(void* const* d_in, const int* in_sizes, int n_in,
                              void* d_out, int out_size) {
    const float* x = (const float*)d_in[0];   // [32][64][8192]
    const float* w = (const float*)d_in[1];   // [64][64][1024]
    float* out = (float*)d_out;               // [32][64][8192]

    init_table_kernel<<<(NLEN + 512) / 512, 512>>>();

    fht_fwd_kernel<<<IROWS, 512>>>(x);

    mix_kernel<<<dim3(33, 4), 256>>>(w);

    fht_inv_kernel<<<OROWS, 512>>>(out);
}

// round 10
// speedup vs baseline: 1.3774x; 1.3774x over previous
#include <cuda_runtime.h>
#include <cstdint>

// Problem constants
#define NLEN   8192
#define LOGN   13
#define MODES  1024
#define BATCH  32
#define CIN    64
#define COUT   64
#define IROWS  (BATCH*CIN)    // 2048 input rows
#define OROWS  (BATCH*COUT)   // 2048 output rows

// -------- scratch (no allocations allowed; use __device__ globals) --------
__device__ __align__(16) float g_xm  [IROWS*MODES];   // [row=b*64+i][m]
__device__ __align__(16) float g_xmT [MODES*IROWS];   // [m][row]
__device__ __align__(16) float g_wT  [MODES*CIN*COUT];// [m][i*64+o]
__device__ __align__(16) float g_zT  [MODES*OROWS];   // [m][b*64+o]
__device__ __align__(16) float g_z   [OROWS*MODES];   // [row=b*64+o][m]

// GF(2)-linear smem swizzle. k0^=u5^u9, k1^=u6^u10, k2^=u7^u11, k3^=u8, k4^=u8^u12.
__device__ __forceinline__ int swz(int u) {
    int f = ((u >> 5) & 7) ^ ((u >> 9) & 7)
          ^ (((u >> 8) & 1) * 0x18)
          ^ (((u >> 12) & 1) * 0x10);
    return u ^ f;
}
__device__ __forceinline__ int rev9(int t) { return (int)(__brev((unsigned)t) >> 23); }

// Literal cas values
#define RSQ2  0.70710678118654752f
#define C8L   0.92387953251128674f
#define S8L   0.38268343236508977f
#define C16A  0.98078528040323044f   // cos(pi/16)
#define S16A  0.19509032201612827f   // sin(pi/16)
#define C16B  0.83146961230254524f   // cos(3pi/16)
#define S16B  0.55557023301960222f   // sin(3pi/16)
#define THETA0 7.66990393942820615e-4f   // pi/4096
#define PHI0   1.22718463030851251e-2f   // pi/256

// Packed f32x2 helpers (Blackwell)
typedef unsigned long long ull_t;
__device__ __forceinline__ ull_t pack2(float x) {
    ull_t r; asm("mov.b64 %0, {%1, %1};" : "=l"(r) : "f"(x)); return r;
}
__device__ __forceinline__ ull_t fma2(ull_t a, ull_t b, ull_t c) {
    ull_t d; asm("fma.rn.f32x2 %0, %1, %2, %3;" : "=l"(d) : "l"(a), "l"(b), "l"(c));
    return d;
}
__device__ __forceinline__ void unpack2(ull_t v, float& lo, float& hi) {
    asm("mov.b64 {%0, %1}, %2;" : "=f"(lo), "=f"(hi) : "l"(v));
}

// Phase-C twiddles via MUFU + double-angle (no memory traffic).
struct CTw { float c13p, c13m, c12p, c12m, c11p, c11m, c10; };
__device__ __forceinline__ CTw ctw(int t) {
    float s1, c1;
    __sincosf((float)t * THETA0, &s1, &c1);
    CTw w;
    w.c13p = c1 + s1;  w.c13m = c1 - s1;
    float s2 = 2.0f * s1 * c1, c2 = fmaf(-2.0f * s1, s1, 1.0f);
    w.c12p = c2 + s2;  w.c12m = c2 - s2;
    float s4 = 2.0f * s2 * c2, c4 = fmaf(-2.0f * s2, s2, 1.0f);
    w.c11p = c4 + s4;  w.c11m = c4 - s4;
    float s8 = 2.0f * s4 * c4, c8 = fmaf(-2.0f * s4, s4, 1.0f);
    w.c10  = c8 + s8;
    return w;
}

// -------- Phase A stages 1-4: all twiddles are literals ---------------------
__device__ __forceinline__ void stagesA(float r[16]) {
    #pragma unroll
    for (int e = 0; e < 16; e += 2) {
        float o = r[e + 1]; r[e + 1] = r[e] - o; r[e] += o;
    }
    #pragma unroll
    for (int g = 0; g < 16; g += 4)
        #pragma unroll
        for (int e = g; e < g + 2; e++) {
            float o = r[e + 2]; r[e + 2] = r[e] - o; r[e] += o;
        }
    {
        const float c3[4] = {1.0f, 1.41421356237309515f, 1.0f, 0.0f};
        #pragma unroll
        for (int eb = 0; eb < 4; eb++)
            #pragma unroll
            for (int g = 0; g < 16; g += 8) {
                int e = g + eb;
                float o = c3[eb] * r[e + 4]; r[e + 4] = r[e] - o; r[e] += o;
            }
    }
    {
        const float c4[8] = {1.0f, 1.30656296487637653f, 1.41421356237309515f,
                             1.30656296487637653f, 1.0f, 0.54119610014619701f,
                             0.0f, -0.54119610014619701f};
        #pragma unroll
        for (int e = 0; e < 8; e++) {
            float o = c4[e] * r[e + 8]; r[e + 8] = r[e] - o; r[e] += o;
        }
    }
}

// -------- Phase B stages 5-9: ALL twiddles from MUFU + literals -------------
// u = lane<<8 | s<<4 | wid. phi = pi*wid/256.
// stage5 cas(16phi); stage6 cas(8phi+sb*pi/2); stage7 cas(4phi+sb*pi/4);
// stage8 cas(2phi+s*pi/8); stage9 cas(phi+s*pi/16).
__device__ __forceinline__ void phaseB(float* sm, float r[16], int t) {
    const int wid  = t >> 5;
    const int lane = t & 31;
    const int base = (lane << 8) | wid;

    float s1, c1;
    __sincosf((float)wid * PHI0, &s1, &c1);
    float p1 = c1 + s1, m1 = c1 - s1;
    float s2 = 2.0f * s1 * c1, c2 = fmaf(-2.0f * s1, s1, 1.0f);
    float p2 = c2 + s2, m2 = c2 - s2;
    float s4 = 2.0f * s2 * c2, c4 = fmaf(-2.0f * s2, s2, 1.0f);
    float p4 = c4 + s4, m4 = c4 - s4;
    float s8 = 2.0f * s4 * c4, c8 = fmaf(-2.0f * s4, s4, 1.0f);
    float p8 = c8 + s8, m8 = c8 - s8;
    float s16 = 2.0f * s8 * c8, c16 = fmaf(-2.0f * s8, s8, 1.0f);
    float p16 = c16 + s16;

    #pragma unroll
    for (int s = 0; s < 16; s++) r[s] = sm[swz(base | (s << 4))];
    // stage 5: cas(16phi)
    #pragma unroll
    for (int s = 0; s < 16; s += 2) {
        float o = p16 * r[s + 1]; r[s + 1] = r[s] - o; r[s] += o;
    }
    // stage 6: {p8, m8}
    {
        const float w6[2] = { p8, m8 };
        #pragma unroll
        for (int sb = 0; sb < 2; sb++)
            #pragma unroll
            for (int g = 0; g < 16; g += 4) {
                int s = g + sb;
                float o = w6[sb] * r[s + 2]; r[s + 2] = r[s] - o; r[s] += o;
            }
    }
    // stage 7: cas(4phi + sb*pi/4)
    {
        const float w7[4] = { p4, RSQ2 * (p4 + m4), m4, RSQ2 * (m4 - p4) };
        #pragma unroll
        for (int sb = 0; sb < 4; sb++)
            #pragma unroll
            for (int g = 0; g < 16; g += 8) {
                int s = g + sb;
                float o = w7[sb] * r[s + 4]; r[s + 4] = r[s] - o; r[s] += o;
            }
    }
    // stage 8: cas(2phi + s*pi/8)
    {
        const float CS[8] = {1.0f, C8L, RSQ2, S8L, 0.0f, -S8L, -RSQ2, -C8L};
        const float SN[8] = {0.0f, S8L, RSQ2, C8L, 1.0f,  C8L,  RSQ2,  S8L};
        #pragma unroll
        for (int s = 0; s < 8; s++) {
            float cas = CS[s] * p2 + SN[s] * m2;
            float o = cas * r[s + 8]; r[s + 8] = r[s] - o; r[s] += o;
        }
    }
    // stage 9: cas(phi + s*pi/16); pairs (lane even, lane odd) via shfl
    {
        const float CS[16] = { 1.0f,  C16A,  C8L,   C16B,  RSQ2,  S16B,  S8L,   S16A,
                               0.0f, -S16A, -S8L,  -S16B, -RSQ2, -C16B, -C8L,  -C16A};
        const float SN[16] = { 0.0f,  S16A,  S8L,   S16B,  RSQ2,  C16B,  C8L,   C16A,
                               1.0f,  C16A,  C8L,   C16B,  RSQ2,  S16B,  S8L,   S16A};
        const bool odd = (lane & 1);
        #pragma unroll
        for (int s = 0; s < 16; s++) {
            float cas = CS[s] * p1 + SN[s] * m1;
            float p = __shfl_xor_sync(0xFFFFFFFFu, r[s], 1);
            r[s] = odd ? (p - cas * r[s]) : fmaf(cas, p, r[s]);
        }
    }
    #pragma unroll
    for (int s = 0; s < 16; s++) sm[swz(base | (s << 4))] = r[s];
}

// -------- forward: x[row][0..8192) -> xm[row][0..1024) ----------------------
__global__ __launch_bounds__(512, 2) void fht_fwd_kernel(const float* __restrict__ x) {
    __shared__ float sm[NLEN];
    const int row = blockIdx.x;
    const int t = threadIdx.x;
    const float* __restrict__ xr = x + (size_t)row * NLEN;

    float r[16];
    {
        const int REV4[16] = {0,8,4,12, 2,10,6,14, 1,9,5,13, 3,11,7,15};
        #pragma unroll
        for (int e = 0; e < 16; e++) r[REV4[e]] = xr[e * 512 + t];
        stagesA(r);
        const int ub = rev9(t) << 4;
        #pragma unroll
        for (int e = 0; e < 16; e++) sm[swz(ub | e)] = r[e];
    }
    __syncthreads();

    phaseB(sm, r, t);
    __syncthreads();

    // Phase C: u = s<<9 | t; stages 10-13 in registers, 11-13 pruned (m<1024)
    {
        CTw w = ctw(t);
        #pragma unroll
        for (int s = 0; s < 16; s++) r[s] = sm[swz((s << 9) | t)];
        #pragma unroll
        for (int s = 0; s < 16; s += 2) {
            float o = w.c10 * r[s + 1]; r[s + 1] = r[s] - o; r[s] += o;
        }
        {
            const float w11[2] = { w.c11p, w.c11m };
            #pragma unroll
            for (int g = 0; g < 16; g += 4)
                #pragma unroll
                for (int sb = 0; sb < 2; sb++)
                    r[g + sb] += w11[sb] * r[g + sb + 2];
        }
        {
            const float w12[2] = { w.c12p, RSQ2 * (w.c12p + w.c12m) };
            #pragma unroll
            for (int g = 0; g < 16; g += 8)
                #pragma unroll
                for (int sb = 0; sb < 2; sb++)
                    r[g + sb] += w12[sb] * r[g + sb + 4];
        }
        r[0] += w.c13p * r[8];
        r[1] += (C8L * w.c13p + S8L * w.c13m) * r[9];

        float* __restrict__ xmr = g_xm + (size_t)row * MODES;
        xmr[t]       = r[0];
        xmr[t + 512] = r[1];
    }
}

// -------- inverse: z[row][0..1024) zero-padded -> out[row][0..8192)/8192 ----
__global__ __launch_bounds__(512, 2) void fht_inv_kernel(float* __restrict__ out) {
    __shared__ float sm[NLEN];
    const int row = blockIdx.x;
    const int t = threadIdx.x;
    const float* __restrict__ zr = g_z + (size_t)row * MODES;

    {
        float v0 = zr[t];
        float v1 = zr[t + 512];
        const int ub = rev9(t) << 4;
        const float c4[8] = {1.0f, 1.30656296487637653f, 1.41421356237309515f,
                             1.30656296487637653f, 1.0f, 0.54119610014619701f,
                             0.0f, -0.54119610014619701f};
        #pragma unroll
        for (int e = 0; e < 8; e++) {
            float o = c4[e] * v1;
            sm[swz(ub | e)]       = v0 + o;
            sm[swz(ub | (e + 8))] = v0 - o;
        }
    }
    __syncthreads();

    float r[16];
    phaseB(sm, r, t);
    __syncthreads();

    {
        CTw w = ctw(t);
        #pragma unroll
        for (int s = 0; s < 16; s++) r[s] = sm[swz((s << 9) | t)];
        #pragma unroll
        for (int s = 0; s < 16; s += 2) {
            float o = w.c10 * r[s + 1]; r[s + 1] = r[s] - o; r[s] += o;
        }
        {
            const float w11[2] = { w.c11p, w.c11m };
            #pragma unroll
            for (int g = 0; g < 16; g += 4)
                #pragma unroll
                for (int sb = 0; sb < 2; sb++) {
                    int s = g + sb;
                    float o = w11[sb] * r[s + 2]; r[s + 2] = r[s] - o; r[s] += o;
                }
        }
        {
            const float w12[4] = { w.c12p, RSQ2 * (w.c12p + w.c12m),
                                   w.c12m, RSQ2 * (w.c12m - w.c12p) };
            #pragma unroll
            for (int g = 0; g < 16; g += 8)
                #pragma unroll
                for (int sb = 0; sb < 4; sb++) {
                    int s = g + sb;
                    float o = w12[sb] * r[s + 4]; r[s + 4] = r[s] - o; r[s] += o;
                }
        }
        {
            const float CS[8] = {1.0f, C8L, RSQ2, S8L, 0.0f, -S8L, -RSQ2, -C8L};
            const float SN[8] = {0.0f, S8L, RSQ2, C8L, 1.0f,  C8L,  RSQ2,  S8L};
            #pragma unroll
            for (int s = 0; s < 8; s++) {
                float w13 = CS[s] * w.c13p + SN[s] * w.c13m;
                float o = w13 * r[s + 8]; r[s + 8] = r[s] - o; r[s] += o;
            }
        }
        const float scale = 1.0f / (float)NLEN;
        float* __restrict__ orow = out + (size_t)row * NLEN;
        #pragma unroll
        for (int s = 0; s < 16; s++)
            orow[(s << 9) | t] = r[s] * scale;
    }
}

// -------- float4 32x32 transpose: src[R][C] -> dst[C][R] --------------------
__global__ __launch_bounds__(256) void transpose4_kernel(const float* __restrict__ src,
                                                         float* __restrict__ dst,
                                                         int R, int C) {
    __shared__ float tile[32][33];
    const int c0 = blockIdx.x * 32, r0 = blockIdx.y * 32;
    const int tid = threadIdx.x;
    const int tx = tid & 7, ty = tid >> 3;

    float4 v = *(const float4*)&src[(size_t)(r0 + ty) * C + c0 + 4 * tx];
    tile[ty][4*tx + 0] = v.x;
    tile[ty][4*tx + 1] = v.y;
    tile[ty][4*tx + 2] = v.z;
    tile[ty][4*tx + 3] = v.w;
    __syncthreads();

    float4 o;
    o.x = tile[4*tx + 0][ty];
    o.y = tile[4*tx + 1][ty];
    o.z = tile[4*tx + 2][ty];
    o.w = tile[4*tx + 3][ty];
    *(float4*)&dst[(size_t)(c0 + ty) * R + r0 + 4 * tx] = o;
}

// -------- paired mode mixing: block m computes z(m) AND z(m') ---------------
__global__ __launch_bounds__(256) void mix_kernel() {
    __shared__ float sa[IROWS];
    __shared__ float sd[IROWS];
    __shared__ float w0[CIN * COUT];
    __shared__ float w1[CIN * COUT];

    const int m  = blockIdx.x;                 // 0..512
    const int mp = (MODES - m) & (MODES - 1);
    const int tid = threadIdx.x;

    const float* xm0 = g_xmT + (size_t)m  * IROWS;
    const float* xm1 = g_xmT + (size_t)mp * IROWS;
    for (int t = tid; t < IROWS; t += 256) {
        float v0 = xm0[t], v1 = xm1[t];
        sa[t] = 0.5f * (v0 + v1);
        sd[t] = 0.5f * (v0 - v1);
    }
    const float* wm0 = g_wT + (size_t)m  * (CIN * COUT);
    const float* wm1 = g_wT + (size_t)mp * (CIN * COUT);
    for (int t = tid; t < CIN * COUT; t += 256) {
        w0[t] = wm0[t];
        w1[t] = wm1[t];
    }
    __syncthreads();

    const int b0 = (tid >> 4) * 2;
    const int o0 = (tid & 15) * 4;

    ull_t A[2][2] = {{0ull, 0ull}, {0ull, 0ull}};
    ull_t B[2][2] = {{0ull, 0ull}, {0ull, 0ull}};

    #pragma unroll 4
    for (int i = 0; i < CIN; i++) {
        float a0 = sa[b0 * CIN + i];
        float a1 = sa[(b0 + 1) * CIN + i];
        float d0 = sd[b0 * CIN + i];
        float d1 = sd[(b0 + 1) * CIN + i];
        ull_t aa0 = pack2(a0), dd0 = pack2(d0), nd0 = pack2(-d0);
        ull_t aa1 = pack2(a1), dd1 = pack2(d1), nd1 = pack2(-d1);
        ull_t w0a = *(const ull_t*)&w0[i * COUT + o0];
        ull_t w0b = *(const ull_t*)&w0[i * COUT + o0 + 2];
        ull_t w1a = *(const ull_t*)&w1[i * COUT + o0];
        ull_t w1b = *(const ull_t*)&w1[i * COUT + o0 + 2];
        A[0][0] = fma2(aa0, w0a, A[0][0]); A[0][0] = fma2(dd0, w1a, A[0][0]);
        A[0][1] = fma2(aa0, w0b, A[0][1]); A[0][1] = fma2(dd0, w1b, A[0][1]);
        A[1][0] = fma2(aa1, w0a, A[1][0]); A[1][0] = fma2(dd1, w1a, A[1][0]);
        A[1][1] = fma2(aa1, w0b, A[1][1]); A[1][1] = fma2(dd1, w1b, A[1][1]);
        B[0][0] = fma2(aa0, w1a, B[0][0]); B[0][0] = fma2(nd0, w0a, B[0][0]);
        B[0][1] = fma2(aa0, w1b, B[0][1]); B[0][1] = fma2(nd0, w0b, B[0][1]);
        B[1][0] = fma2(aa1, w1a, B[1][0]); B[1][0] = fma2(nd1, w0a, B[1][0]);
        B[1][1] = fma2(aa1, w1b, B[1][1]); B[1][1] = fma2(nd1, w0b, B[1][1]);
    }

    float* zr = g_zT + (size_t)m * OROWS;
    #pragma unroll
    for (int bb = 0; bb < 2; bb++) {
        float x0, x1, x2, x3;
        unpack2(A[bb][0], x0, x1);
        unpack2(A[bb][1], x2, x3);
        zr[(b0+bb)*COUT + o0 + 0] = x0; zr[(b0+bb)*COUT + o0 + 1] = x1;
        zr[(b0+bb)*COUT + o0 + 2] = x2; zr[(b0+bb)*COUT + o0 + 3] = x3;
    }
    if (mp != m) {
        float* zp = g_zT + (size_t)mp * OROWS;
        #pragma unroll
        for (int bb = 0; bb < 2; bb++) {
            float x0, x1, x2, x3;
            unpack2(B[bb][0], x0, x1);
            unpack2(B[bb][1], x2, x3);
            zp[(b0+bb)*COUT + o0 + 0] = x0; zp[(b0+bb)*COUT + o0 + 1] = x1;
            zp[(b0+bb)*COUT + o0 + 2] = x2; zp[(b0+bb)*COUT + o0 + 3] = x3;
        }
    }
}

// ---------------------------------------------------------------------------
extern "C" void kernel_launch(void* const* d_in, const int* in_sizes, int n_in,
                              void* d_out, int out_size) {
    const float* x = (const float*)d_in[0];   // [32][64][8192]
    const float* w = (const float*)d_in[1];   // [64][64][1024]
    float* out = (float*)d_out;               // [32][64][8192]

    float* xm  = nullptr; cudaGetSymbolAddress((void**)&xm,  g_xm);
    float* xmT = nullptr; cudaGetSymbolAddress((void**)&xmT, g_xmT);
    float* wT  = nullptr; cudaGetSymbolAddress((void**)&wT,  g_wT);
    float* zT  = nullptr; cudaGetSymbolAddress((void**)&zT,  g_zT);
    float* z   = nullptr; cudaGetSymbolAddress((void**)&z,   g_z);

    fht_fwd_kernel<<<IROWS, 512>>>(x);

    // xm [2048][1024] -> xmT [1024][2048]
    transpose4_kernel<<<dim3(MODES / 32, IROWS / 32), 256>>>(xm, xmT, IROWS, MODES);
    // w  [4096][1024] -> wT  [1024][4096]
    transpose4_kernel<<<dim3(MODES / 32, (CIN * COUT) / 32), 256>>>(w, wT, CIN * COUT, MODES);

    mix_kernel<<<MODES / 2 + 1, 256>>>();     // 513 blocks: m and m' paired

    // zT [1024][2048] -> z [2048][1024]
    transpose4_kernel<<<dim3(OROWS / 32, MODES / 32), 256>>>(zT, z, MODES, OROWS);

    fht_inv_kernel<<<OROWS, 512>>>(out);
}